// round 14
// baseline (speedup 1.0000x reference)
#include <cuda_runtime.h>
#include <cuda_bf16.h>
#include <mma.h>
#include <cstdint>
#include <math.h>

using namespace nvcuda;

#define NMAX 100000
#define NPAD 100096      // 782*128
#define EMAX 1600000
#define DIMF 128

// ---------------- static scratch (no allocations allowed) ----------------
__device__ __align__(16) float g_h0 [(size_t)NPAD * DIMF];
__device__ __align__(16) float g_h1 [(size_t)NPAD * DIMF];
// bf16 split tables (hi/lo), padded rows zero-initialized (bss)
__device__ __align__(16) __nv_bfloat16 g_aggH[(size_t)NPAD * DIMF];
__device__ __align__(16) __nv_bfloat16 g_aggL[(size_t)NPAD * DIMF];
__device__ __align__(16) __nv_bfloat16 g_xH  [(size_t)NPAD * DIMF];
__device__ __align__(16) __nv_bfloat16 g_xL  [(size_t)NPAD * DIMF];
__device__ __align__(16) __nv_bfloat16 g_hH  [(size_t)NPAD * DIMF];
__device__ __align__(16) __nv_bfloat16 g_hL  [(size_t)NPAD * DIMF];
// weights transposed+concatenated: [128 rows (out col), 256 cols (k)] bf16
__device__ __align__(16) __nv_bfloat16 g_WtH[128 * 256];
__device__ __align__(16) __nv_bfloat16 g_WtL[128 * 256];

__device__ int   g_cnt[NMAX];
__device__ int   g_rowptr[NMAX + 1];
__device__ int   g_cursor[NMAX];
__device__ int   g_csr[EMAX];
__device__ int   g_bsum[128];
__device__ int   g_bsumx[128];
__device__ __align__(16) float g_colsum[DIMF];
__device__ __align__(16) float g_colsq[DIMF];

// sel: 0 = external ptr, 1 = g_h0, 2 = g_h1
__device__ __forceinline__ const float* sel_in(int s, const float* ext) {
    if (s == 1) return g_h0;
    if (s == 2) return g_h1;
    return ext;
}
__device__ __forceinline__ float* sel_out(int s, float* ext) {
    if (s == 1) return g_h0;
    if (s == 2) return g_h1;
    return ext;
}

// split a float into bf16 hi + bf16 lo
__device__ __forceinline__ void split2(float a, __nv_bfloat16& h, __nv_bfloat16& l) {
    h = __float2bfloat16(a);
    l = __float2bfloat16(a - __bfloat162float(h));
}

// ---------------- conversions (k_convX also zeroes g_cnt for CSR build) ----------------
__global__ void k_convX(const float* __restrict__ x, int Nrows) {
    int idx = blockIdx.x * blockDim.x + threadIdx.x;  // float4 index
    // fold CSR-count zeroing in here (runs before k_hist)
    if (idx < NMAX) g_cnt[idx] = 0;
    int idx2 = idx + (int)(gridDim.x * blockDim.x);
    if (idx2 < NMAX) g_cnt[idx2] = 0;
    if (idx >= Nrows * 32) return;
    float4 v = ((const float4*)x)[idx];
    union { __nv_bfloat16 h[4]; uint2 u; } ph, pl;
    split2(v.x, ph.h[0], pl.h[0]);
    split2(v.y, ph.h[1], pl.h[1]);
    split2(v.z, ph.h[2], pl.h[2]);
    split2(v.w, ph.h[3], pl.h[3]);
    ((uint2*)g_xH)[idx] = ph.u;
    ((uint2*)g_xL)[idx] = pl.u;
}

// weights: Wt[n][k] = k<128 ? Wl[k][n] : Wr[k-128][n], n beyond Ncol -> 0
// also zeroes BN column accumulators for this layer (safe: runs before bnreduce)
__global__ void k_convW(const float* __restrict__ Wl, const float* __restrict__ Wr, int Ncol) {
    int idx = blockIdx.x * blockDim.x + threadIdx.x;  // over 128*256
    if (blockIdx.x == 0 && threadIdx.x < DIMF) {
        g_colsum[threadIdx.x] = 0.f;
        g_colsq[threadIdx.x]  = 0.f;
    }
    if (idx >= 128 * 256) return;
    int n = idx >> 8, k = idx & 255;
    float v = 0.f;
    if (n < Ncol) v = (k < 128) ? Wl[k * Ncol + n] : Wr[(k - 128) * Ncol + n];
    __nv_bfloat16 h, l;
    split2(v, h, l);
    g_WtH[idx] = h;
    g_WtL[idx] = l;
}

// ---------------- CSR build ----------------
__global__ void k_hist(const int* __restrict__ dst, int E, int n) {
    int e = blockIdx.x * blockDim.x + threadIdx.x;
    if (e < E) {
        unsigned d = (unsigned)dst[e];
        if (d < (unsigned)n) atomicAdd(&g_cnt[d], 1);
    }
}
__global__ __launch_bounds__(1024) void k_scan1(int n) {
    __shared__ int s[1024];
    int i = blockIdx.x * 1024 + threadIdx.x;
    int v = (i < n) ? g_cnt[i] : 0;
    s[threadIdx.x] = v;
    __syncthreads();
    #pragma unroll
    for (int off = 1; off < 1024; off <<= 1) {
        int t = (threadIdx.x >= off) ? s[threadIdx.x - off] : 0;
        __syncthreads();
        s[threadIdx.x] += t;
        __syncthreads();
    }
    if (i < n) g_rowptr[i] = s[threadIdx.x] - v;
    if (threadIdx.x == 1023) g_bsum[blockIdx.x] = s[1023];
}
__global__ void k_scan2(int nb) {
    __shared__ int s[128];
    int v = (threadIdx.x < nb) ? g_bsum[threadIdx.x] : 0;
    s[threadIdx.x] = v;
    __syncthreads();
    #pragma unroll
    for (int off = 1; off < 128; off <<= 1) {
        int t = (threadIdx.x >= off) ? s[threadIdx.x - off] : 0;
        __syncthreads();
        s[threadIdx.x] += t;
        __syncthreads();
    }
    if (threadIdx.x < nb) g_bsumx[threadIdx.x] = s[threadIdx.x] - v;
}
__global__ __launch_bounds__(1024) void k_scan3(int n, int E) {
    int i = blockIdx.x * 1024 + threadIdx.x;
    if (i < n) {
        int v = g_rowptr[i] + g_bsumx[i >> 10];
        g_rowptr[i] = v;
        g_cursor[i] = v;
    }
    if (i == 0) g_rowptr[n] = E;
}
__global__ void k_fill(const int* __restrict__ src, const int* __restrict__ dst, int E, int n) {
    int e = blockIdx.x * blockDim.x + threadIdx.x;
    if (e < E) {
        unsigned d = (unsigned)dst[e];
        unsigned s = (unsigned)src[e];
        if (d < (unsigned)n && s < (unsigned)n) {
            int p = atomicAdd(&g_cursor[d], 1);
            g_csr[p] = (int)s;
        }
    }
}

// ---------------- mean aggregation -> bf16 split tables ----------------
// warp per node; indices staged warp-cooperatively (1 coalesced load per 32
// edges, shfl broadcast), gathers unrolled x4 for MLP.
__global__ void k_aggregate(const float* __restrict__ ext, int selIn, int n) {
    int gw   = (blockIdx.x * blockDim.x + threadIdx.x) >> 5;
    int lane = threadIdx.x & 31;
    if (gw >= n) return;
    const float4* base = (const float4*)sel_in(selIn, ext);
    int s0 = g_rowptr[gw], s1 = g_rowptr[gw + 1];
    float4 a0 = make_float4(0.f, 0.f, 0.f, 0.f);
    float4 a1 = make_float4(0.f, 0.f, 0.f, 0.f);

    for (int b = s0; b < s1; b += 32) {
        int cnt = min(32, s1 - b);
        int myidx = (lane < cnt) ? __ldg(&g_csr[b + lane]) : 0;
        int j = 0;
        for (; j + 4 <= cnt; j += 4) {
            int i0 = __shfl_sync(0xffffffffu, myidx, j);
            int i1 = __shfl_sync(0xffffffffu, myidx, j + 1);
            int i2 = __shfl_sync(0xffffffffu, myidx, j + 2);
            int i3 = __shfl_sync(0xffffffffu, myidx, j + 3);
            float4 v0 = __ldg(&base[(size_t)i0 * 32 + lane]);
            float4 v1 = __ldg(&base[(size_t)i1 * 32 + lane]);
            float4 v2 = __ldg(&base[(size_t)i2 * 32 + lane]);
            float4 v3 = __ldg(&base[(size_t)i3 * 32 + lane]);
            a0.x += v0.x; a0.y += v0.y; a0.z += v0.z; a0.w += v0.w;
            a1.x += v1.x; a1.y += v1.y; a1.z += v1.z; a1.w += v1.w;
            a0.x += v2.x; a0.y += v2.y; a0.z += v2.z; a0.w += v2.w;
            a1.x += v3.x; a1.y += v3.y; a1.z += v3.z; a1.w += v3.w;
        }
        for (; j < cnt; j++) {
            int i0 = __shfl_sync(0xffffffffu, myidx, j);
            float4 v0 = __ldg(&base[(size_t)i0 * 32 + lane]);
            a0.x += v0.x; a0.y += v0.y; a0.z += v0.z; a0.w += v0.w;
        }
    }
    float inv = 1.f / fmaxf((float)(s1 - s0), 1.f);
    float4 acc;
    acc.x = (a0.x + a1.x) * inv;
    acc.y = (a0.y + a1.y) * inv;
    acc.z = (a0.z + a1.z) * inv;
    acc.w = (a0.w + a1.w) * inv;
    union { __nv_bfloat16 h[4]; uint2 u; } ph, pl;
    split2(acc.x, ph.h[0], pl.h[0]);
    split2(acc.y, ph.h[1], pl.h[1]);
    split2(acc.z, ph.h[2], pl.h[2]);
    split2(acc.w, ph.h[3], pl.h[3]);
    size_t o = (size_t)gw * 32 + lane;
    ((uint2*)g_aggH)[o] = ph.u;
    ((uint2*)g_aggL)[o] = pl.u;
}

// ---------------- WMMA bf16x3 GEMM ----------------
// out[128, 64-tile] = [agg | X](128x256) @ Wt(ncol x 256)^T
// 8 warps: 4x2 grid of 32x32 warp tiles. K staged in 8 chunks of 32.
// Layers 0/1 (Ncol==128): bias folded out by BN invariance, direct global store.
// Layer 2 (Ncol==47): bias + log_softmax fused in epilogue via smem.
#define AST 40   // smem row stride (bf16 elems) for A (32 + 8 pad)
#define BST 40

__global__ __launch_bounds__(256) void k_mma(
    int selX, const float* __restrict__ bias,
    float* __restrict__ extOut, int selOut,
    int Nrows, int Ncol)
{
    __shared__ __align__(16) char smemU[131072 / 4];  // 32 KB overlay
    __nv_bfloat16* sAH = (__nv_bfloat16*)smemU;       // 128*40 = 5120 elems
    __nv_bfloat16* sAL = sAH + 128 * AST;
    __nv_bfloat16* sBH = sAL + 128 * AST;             // 64*40 elems
    __nv_bfloat16* sBL = sBH + 64 * BST;
    float* sE = (float*)smemU;                        // 128*64 f32 overlay (epilogue)

    int tid = threadIdx.x;
    int wid = tid >> 5, lid = tid & 31;
    int tileM = blockIdx.x * 128;
    int tileN = blockIdx.y * 64;
    int warpM = wid >> 1;   // 0..3
    int warpN = wid & 1;    // 0..1

    const __nv_bfloat16* XH = selX ? g_hH : g_xH;
    const __nv_bfloat16* XL = selX ? g_hL : g_xL;

    wmma::fragment<wmma::accumulator, 16, 16, 16, float> acc[2][2];
    #pragma unroll
    for (int m = 0; m < 2; m++)
        #pragma unroll
        for (int n = 0; n < 2; n++)
            wmma::fill_fragment(acc[m][n], 0.f);

    for (int chunk = 0; chunk < 8; chunk++) {
        const __nv_bfloat16* tAH = (chunk < 4) ? g_aggH : XH;
        const __nv_bfloat16* tAL = (chunk < 4) ? g_aggL : XL;
        int colA = (chunk & 3) * 32;

        // A: 128 rows x 32 cols, hi+lo (512 uint4 each)
        #pragma unroll
        for (int it = 0; it < 2; it++) {
            int u = it * 256 + tid;
            int r = u >> 2, c8 = (u & 3) * 8;
            size_t g = (size_t)(tileM + r) * 128 + colA + c8;
            *(uint4*)(sAH + r * AST + c8) = *(const uint4*)(tAH + g);
            *(uint4*)(sAL + r * AST + c8) = *(const uint4*)(tAL + g);
        }
        // B: 64 rows x 32 cols, hi+lo (256 uint4 each)
        {
            int r = tid >> 2, c8 = (tid & 3) * 8;
            size_t g = (size_t)(tileN + r) * 256 + chunk * 32 + c8;
            *(uint4*)(sBH + r * BST + c8) = *(const uint4*)(g_WtH + g);
            *(uint4*)(sBL + r * BST + c8) = *(const uint4*)(g_WtL + g);
        }
        __syncthreads();

        #pragma unroll
        for (int ks = 0; ks < 2; ks++) {
            int kb = ks * 16;
            wmma::fragment<wmma::matrix_a, 16, 16, 16, __nv_bfloat16, wmma::row_major> aH[2], aL[2];
            wmma::fragment<wmma::matrix_b, 16, 16, 16, __nv_bfloat16, wmma::col_major> bH[2], bL[2];
            #pragma unroll
            for (int m = 0; m < 2; m++) {
                wmma::load_matrix_sync(aH[m], sAH + (warpM * 32 + m * 16) * AST + kb, AST);
                wmma::load_matrix_sync(aL[m], sAL + (warpM * 32 + m * 16) * AST + kb, AST);
            }
            #pragma unroll
            for (int n = 0; n < 2; n++) {
                wmma::load_matrix_sync(bH[n], sBH + (warpN * 32 + n * 16) * BST + kb, BST);
                wmma::load_matrix_sync(bL[n], sBL + (warpN * 32 + n * 16) * BST + kb, BST);
            }
            #pragma unroll
            for (int m = 0; m < 2; m++)
                #pragma unroll
                for (int n = 0; n < 2; n++) {
                    wmma::mma_sync(acc[m][n], aH[m], bH[n], acc[m][n]);
                    wmma::mma_sync(acc[m][n], aH[m], bL[n], acc[m][n]);
                    wmma::mma_sync(acc[m][n], aL[m], bH[n], acc[m][n]);
                }
        }
        __syncthreads();
    }

    if (Ncol == 128) {
        // bias dropped (BN-invariant); h buffers are NPAD rows -> no row guard
        float* outp = sel_out(selOut, extOut);
        #pragma unroll
        for (int m = 0; m < 2; m++)
            #pragma unroll
            for (int n = 0; n < 2; n++)
                wmma::store_matrix_sync(
                    outp + (size_t)(tileM + warpM * 32 + m * 16) * 128
                         + tileN + warpN * 32 + n * 16,
                    acc[m][n], 128, wmma::mem_row_major);
    } else {
        // layer 2: stash to smem, then fused bias + log_softmax
        #pragma unroll
        for (int m = 0; m < 2; m++)
            #pragma unroll
            for (int n = 0; n < 2; n++)
                wmma::store_matrix_sync(
                    sE + (warpM * 32 + m * 16) * 64 + warpN * 32 + n * 16,
                    acc[m][n], 64, wmma::mem_row_major);
        __syncthreads();

        for (int i = 0; i < 16; i++) {
            int r = wid * 16 + i;
            int row = tileM + r;
            float v0 = (lid < 47)      ? sE[r * 64 + lid]      + bias[lid]      : -1e30f;
            float v1 = (lid + 32 < 47) ? sE[r * 64 + lid + 32] + bias[lid + 32] : -1e30f;
            float mx = fmaxf(v0, v1);
            #pragma unroll
            for (int off = 16; off > 0; off >>= 1)
                mx = fmaxf(mx, __shfl_xor_sync(0xffffffffu, mx, off));
            float s = ((lid < 47) ? expf(v0 - mx) : 0.f) + ((lid + 32 < 47) ? expf(v1 - mx) : 0.f);
            #pragma unroll
            for (int off = 16; off > 0; off >>= 1)
                s += __shfl_xor_sync(0xffffffffu, s, off);
            float l = mx + logf(s);
            if (row < Nrows) {
                if (lid < 47)      extOut[(size_t)row * 47 + lid]      = v0 - l;
                if (lid + 32 < 47) extOut[(size_t)row * 47 + lid + 32] = v1 - l;
            }
        }
    }
}

// ---------------- BatchNorm ----------------
__global__ void k_bnreduce(int selH, int Nrows) {
    const float* h = sel_in(selH, (const float*)0);
    __shared__ float ssum[256], ssq[256];
    int col  = threadIdx.x & 127;
    int half = threadIdx.x >> 7;
    float s = 0.f, q = 0.f;
    for (int r = blockIdx.x * 2 + half; r < Nrows; r += gridDim.x * 2) {
        float v = h[(size_t)r * DIMF + col];
        s += v; q += v * v;
    }
    ssum[threadIdx.x] = s; ssq[threadIdx.x] = q;
    __syncthreads();
    if (threadIdx.x < 128) {
        atomicAdd(&g_colsum[col], ssum[threadIdx.x] + ssum[threadIdx.x + 128]);
        atomicAdd(&g_colsq[col],  ssq[threadIdx.x]  + ssq[threadIdx.x + 128]);
    }
}
// bn+relu (scale/shift derived in-block from colsum/colsq; no bnfinal kernel).
// writes fp32 h (for aggregation) AND bf16 splits (next GEMM X operand)
__global__ void k_bnapply(int selH, const float* __restrict__ gw,
                          const float* __restrict__ be, int Nrows) {
    __shared__ float s_scale[DIMF], s_shift[DIMF];
    if (threadIdx.x < DIMF) {
        int i = threadIdx.x;
        float invn = 1.f / (float)Nrows;
        float mu  = g_colsum[i] * invn;
        float var = g_colsq[i] * invn - mu * mu;
        float rs  = rsqrtf(var + 1e-5f);
        float sc  = rs * gw[i];
        s_scale[i] = sc;
        s_shift[i] = be[i] - mu * sc;
    }
    __syncthreads();
    float* h = sel_out(selH, (float*)0);
    int idx = blockIdx.x * blockDim.x + threadIdx.x;  // float4 index
    if (idx >= Nrows * 32) return;
    int col = (idx * 4) & 127;
    float4 v  = ((float4*)h)[idx];
    float4 sc = *(const float4*)&s_scale[col];
    float4 sh = *(const float4*)&s_shift[col];
    v.x = fmaxf(v.x * sc.x + sh.x, 0.f);
    v.y = fmaxf(v.y * sc.y + sh.y, 0.f);
    v.z = fmaxf(v.z * sc.z + sh.z, 0.f);
    v.w = fmaxf(v.w * sc.w + sh.w, 0.f);
    ((float4*)h)[idx] = v;
    union { __nv_bfloat16 b[4]; uint2 u; } ph, pl;
    split2(v.x, ph.b[0], pl.b[0]);
    split2(v.y, ph.b[1], pl.b[1]);
    split2(v.z, ph.b[2], pl.b[2]);
    split2(v.w, ph.b[3], pl.b[3]);
    ((uint2*)g_hH)[idx] = ph.u;
    ((uint2*)g_hL)[idx] = pl.u;
}

// ---------------- driver ----------------
extern "C" void kernel_launch(void* const* d_in, const int* in_sizes, int n_in,
                              void* d_out, int out_size) {
    const float* x  = (const float*)d_in[0];
    const int*   ei = (const int*)d_in[1];   // int32 (JAX x64-disabled)
    const float* Wl0 = (const float*)d_in[2];
    const float* bl0 = (const float*)d_in[3];
    const float* Wr0 = (const float*)d_in[4];
    const float* g0  = (const float*)d_in[5];
    const float* be0 = (const float*)d_in[6];
    const float* Wl1 = (const float*)d_in[7];
    const float* bl1 = (const float*)d_in[8];
    const float* Wr1 = (const float*)d_in[9];
    const float* g1  = (const float*)d_in[10];
    const float* be1 = (const float*)d_in[11];
    const float* Wl2 = (const float*)d_in[12];
    const float* bl2 = (const float*)d_in[13];
    const float* Wr2 = (const float*)d_in[14];
    float* out = (float*)d_out;

    int N = in_sizes[0] / DIMF;
    int E = in_sizes[1] / 2;
    if (N > NMAX) N = NMAX;
    if (E > EMAX) E = EMAX;
    const int* srcp = ei;
    const int* dstp = ei + E;
    (void)bl0; (void)bl1;  // folded out by BN invariance

    int nb1024     = (N + 1023) / 1024;
    int aggBlocks  = (N + 7) / 8;
    int mTiles     = (N + 127) / 128;
    int convBlocks = (N * 32 + 255) / 256;
    dim3 gemmGrid2(mTiles, 2);   // Ncol=128
    dim3 gemmGrid1(mTiles, 1);   // Ncol=47

    // --- convX (also zeroes g_cnt), then CSR build ---
    k_convX<<<convBlocks, 256>>>(x, N);
    k_hist<<<(E + 255) / 256, 256>>>(dstp, E, N);
    k_scan1<<<nb1024, 1024>>>(N);
    k_scan2<<<1, 128>>>(nb1024);
    k_scan3<<<nb1024, 1024>>>(N, E);
    k_fill<<<(E + 255) / 256, 256>>>(srcp, dstp, E, N);

    // --- layer 0: agg(x) -> splits; h0 = mma(aggS, xS) ---
    k_convW<<<(128 * 256 + 255) / 256, 256>>>(Wl0, Wr0, 128);
    k_aggregate<<<aggBlocks, 256>>>(x, 0, N);
    k_mma<<<gemmGrid2, 256>>>(0, bl0, (float*)0, 1, N, 128);
    k_bnreduce<<<512, 256>>>(1, N);
    k_bnapply<<<convBlocks, 256>>>(1, g0, be0, N);

    // --- layer 1: agg(h0); h1 = mma(aggS, hS) ---
    k_convW<<<(128 * 256 + 255) / 256, 256>>>(Wl1, Wr1, 128);
    k_aggregate<<<aggBlocks, 256>>>((const float*)0, 1, N);
    k_mma<<<gemmGrid2, 256>>>(1, bl1, (float*)0, 2, N, 128);
    k_bnreduce<<<512, 256>>>(2, N);
    k_bnapply<<<convBlocks, 256>>>(2, g1, be1, N);

    // --- layer 2: agg(h1); out = log_softmax(mma(aggS, hS) + bias) (fused) ---
    k_convW<<<(128 * 256 + 255) / 256, 256>>>(Wl2, Wr2, 47);
    k_aggregate<<<aggBlocks, 256>>>((const float*)0, 2, N);
    k_mma<<<gemmGrid1, 256>>>(1, bl2, out, 0, N, 47);
}

// round 15
// speedup vs baseline: 1.0489x; 1.0489x over previous
#include <cuda_runtime.h>
#include <cuda_bf16.h>
#include <mma.h>
#include <cstdint>
#include <math.h>

using namespace nvcuda;

#define NMAX 100000
#define NPAD 100096      // 782*128
#define EMAX 1600000
#define DIMF 128

// ---------------- static scratch (no allocations allowed) ----------------
__device__ __align__(16) float g_h0 [(size_t)NPAD * DIMF];
__device__ __align__(16) float g_h1 [(size_t)NPAD * DIMF];
// bf16 split tables (hi/lo), padded rows zero-initialized (bss)
__device__ __align__(16) __nv_bfloat16 g_aggH[(size_t)NPAD * DIMF];
__device__ __align__(16) __nv_bfloat16 g_aggL[(size_t)NPAD * DIMF];
__device__ __align__(16) __nv_bfloat16 g_xH  [(size_t)NPAD * DIMF];
__device__ __align__(16) __nv_bfloat16 g_xL  [(size_t)NPAD * DIMF];
__device__ __align__(16) __nv_bfloat16 g_hH  [(size_t)NPAD * DIMF];
__device__ __align__(16) __nv_bfloat16 g_hL  [(size_t)NPAD * DIMF];
// weights transposed+concatenated: [128 rows (out col), 256 cols (k)] bf16
__device__ __align__(16) __nv_bfloat16 g_WtH[128 * 256];
__device__ __align__(16) __nv_bfloat16 g_WtL[128 * 256];

__device__ int   g_cnt[NMAX];
__device__ int   g_rowptr[NMAX + 1];
__device__ int   g_cursor[NMAX];
__device__ int   g_csr[EMAX];
__device__ int   g_bsum[128];
__device__ int   g_bsumx[128];
__device__ __align__(16) float g_colsum[DIMF];
__device__ __align__(16) float g_colsq[DIMF];

// sel: 0 = external ptr, 1 = g_h0, 2 = g_h1
__device__ __forceinline__ const float* sel_in(int s, const float* ext) {
    if (s == 1) return g_h0;
    if (s == 2) return g_h1;
    return ext;
}
__device__ __forceinline__ float* sel_out(int s, float* ext) {
    if (s == 1) return g_h0;
    if (s == 2) return g_h1;
    return ext;
}

// split a float into bf16 hi + bf16 lo
__device__ __forceinline__ void split2(float a, __nv_bfloat16& h, __nv_bfloat16& l) {
    h = __float2bfloat16(a);
    l = __float2bfloat16(a - __bfloat162float(h));
}

// ---------------- conversions (k_convX also zeroes g_cnt for CSR build) ----------------
__global__ void k_convX(const float* __restrict__ x, int Nrows) {
    int idx = blockIdx.x * blockDim.x + threadIdx.x;  // float4 index
    // fold CSR-count zeroing in here (runs before k_hist)
    if (idx < NMAX) g_cnt[idx] = 0;
    int idx2 = idx + (int)(gridDim.x * blockDim.x);
    if (idx2 < NMAX) g_cnt[idx2] = 0;
    if (idx >= Nrows * 32) return;
    float4 v = ((const float4*)x)[idx];
    union { __nv_bfloat16 h[4]; uint2 u; } ph, pl;
    split2(v.x, ph.h[0], pl.h[0]);
    split2(v.y, ph.h[1], pl.h[1]);
    split2(v.z, ph.h[2], pl.h[2]);
    split2(v.w, ph.h[3], pl.h[3]);
    ((uint2*)g_xH)[idx] = ph.u;
    ((uint2*)g_xL)[idx] = pl.u;
}

// weights: Wt[n][k] = k<128 ? Wl[k][n] : Wr[k-128][n], n beyond Ncol -> 0
// also zeroes BN column accumulators for this layer (safe: runs before bnreduce)
__global__ void k_convW(const float* __restrict__ Wl, const float* __restrict__ Wr, int Ncol) {
    int idx = blockIdx.x * blockDim.x + threadIdx.x;  // over 128*256
    if (blockIdx.x == 0 && threadIdx.x < DIMF) {
        g_colsum[threadIdx.x] = 0.f;
        g_colsq[threadIdx.x]  = 0.f;
    }
    if (idx >= 128 * 256) return;
    int n = idx >> 8, k = idx & 255;
    float v = 0.f;
    if (n < Ncol) v = (k < 128) ? Wl[k * Ncol + n] : Wr[(k - 128) * Ncol + n];
    __nv_bfloat16 h, l;
    split2(v, h, l);
    g_WtH[idx] = h;
    g_WtL[idx] = l;
}

// ---------------- CSR build ----------------
__global__ void k_hist(const int* __restrict__ dst, int E, int n) {
    int e = blockIdx.x * blockDim.x + threadIdx.x;
    if (e < E) {
        unsigned d = (unsigned)dst[e];
        if (d < (unsigned)n) atomicAdd(&g_cnt[d], 1);
    }
}
__global__ __launch_bounds__(1024) void k_scan1(int n) {
    __shared__ int s[1024];
    int i = blockIdx.x * 1024 + threadIdx.x;
    int v = (i < n) ? g_cnt[i] : 0;
    s[threadIdx.x] = v;
    __syncthreads();
    #pragma unroll
    for (int off = 1; off < 1024; off <<= 1) {
        int t = (threadIdx.x >= off) ? s[threadIdx.x - off] : 0;
        __syncthreads();
        s[threadIdx.x] += t;
        __syncthreads();
    }
    if (i < n) g_rowptr[i] = s[threadIdx.x] - v;
    if (threadIdx.x == 1023) g_bsum[blockIdx.x] = s[1023];
}
__global__ void k_scan2(int nb) {
    __shared__ int s[128];
    int v = (threadIdx.x < nb) ? g_bsum[threadIdx.x] : 0;
    s[threadIdx.x] = v;
    __syncthreads();
    #pragma unroll
    for (int off = 1; off < 128; off <<= 1) {
        int t = (threadIdx.x >= off) ? s[threadIdx.x - off] : 0;
        __syncthreads();
        s[threadIdx.x] += t;
        __syncthreads();
    }
    if (threadIdx.x < nb) g_bsumx[threadIdx.x] = s[threadIdx.x] - v;
}
__global__ __launch_bounds__(1024) void k_scan3(int n, int E) {
    int i = blockIdx.x * 1024 + threadIdx.x;
    if (i < n) {
        int v = g_rowptr[i] + g_bsumx[i >> 10];
        g_rowptr[i] = v;
        g_cursor[i] = v;
    }
    if (i == 0) g_rowptr[n] = E;
}
__global__ void k_fill(const int* __restrict__ src, const int* __restrict__ dst, int E, int n) {
    int e = blockIdx.x * blockDim.x + threadIdx.x;
    if (e < E) {
        unsigned d = (unsigned)dst[e];
        unsigned s = (unsigned)src[e];
        if (d < (unsigned)n && s < (unsigned)n) {
            int p = atomicAdd(&g_cursor[d], 1);
            g_csr[p] = (int)s;
        }
    }
}

// ---------------- mean aggregation -> bf16 split tables ----------------
// 1 warp per node, float4 per lane. Scalar index loads are warp-uniform
// broadcasts; successive row gathers are independent (MLP high). This loop is
// LTS-bandwidth-bound — round 14's shuffle-staged variant was SLOWER.
__global__ void k_aggregate(const float* __restrict__ ext, int selIn, int n) {
    int gw   = (blockIdx.x * blockDim.x + threadIdx.x) >> 5;
    int lane = threadIdx.x & 31;
    if (gw >= n) return;
    const float* in = sel_in(selIn, ext);
    int s0 = g_rowptr[gw], s1 = g_rowptr[gw + 1];
    float4 acc = make_float4(0.f, 0.f, 0.f, 0.f);
    const float4* base = (const float4*)in;
    for (int e = s0; e < s1; e++) {
        int s = g_csr[e];
        float4 v = __ldg(&base[(size_t)s * 32 + lane]);
        acc.x += v.x; acc.y += v.y; acc.z += v.z; acc.w += v.w;
    }
    float inv = 1.f / fmaxf((float)(s1 - s0), 1.f);
    acc.x *= inv; acc.y *= inv; acc.z *= inv; acc.w *= inv;
    union { __nv_bfloat16 h[4]; uint2 u; } ph, pl;
    split2(acc.x, ph.h[0], pl.h[0]);
    split2(acc.y, ph.h[1], pl.h[1]);
    split2(acc.z, ph.h[2], pl.h[2]);
    split2(acc.w, ph.h[3], pl.h[3]);
    size_t o = (size_t)gw * 32 + lane;
    ((uint2*)g_aggH)[o] = ph.u;
    ((uint2*)g_aggL)[o] = pl.u;
}

// ---------------- WMMA bf16x3 GEMM ----------------
// out[128, 64-tile] = [agg | X](128x256) @ Wt(ncol x 256)^T
// 8 warps: 4x2 grid of 32x32 warp tiles. K staged in 8 chunks of 32.
// Layers 0/1 (Ncol==128): bias folded out by BN invariance, direct global store.
// Layer 2 (Ncol==47): bias + log_softmax fused in epilogue via smem.
#define AST 40   // smem row stride (bf16 elems) for A (32 + 8 pad)
#define BST 40

__global__ __launch_bounds__(256) void k_mma(
    int selX, const float* __restrict__ bias,
    float* __restrict__ extOut, int selOut,
    int Nrows, int Ncol)
{
    __shared__ __align__(16) char smemU[131072 / 4];  // 32 KB overlay
    __nv_bfloat16* sAH = (__nv_bfloat16*)smemU;       // 128*40 = 5120 elems
    __nv_bfloat16* sAL = sAH + 128 * AST;
    __nv_bfloat16* sBH = sAL + 128 * AST;             // 64*40 elems
    __nv_bfloat16* sBL = sBH + 64 * BST;
    float* sE = (float*)smemU;                        // 128*64 f32 overlay (epilogue)

    int tid = threadIdx.x;
    int wid = tid >> 5, lid = tid & 31;
    int tileM = blockIdx.x * 128;
    int tileN = blockIdx.y * 64;
    int warpM = wid >> 1;   // 0..3
    int warpN = wid & 1;    // 0..1

    const __nv_bfloat16* XH = selX ? g_hH : g_xH;
    const __nv_bfloat16* XL = selX ? g_hL : g_xL;

    wmma::fragment<wmma::accumulator, 16, 16, 16, float> acc[2][2];
    #pragma unroll
    for (int m = 0; m < 2; m++)
        #pragma unroll
        for (int n = 0; n < 2; n++)
            wmma::fill_fragment(acc[m][n], 0.f);

    for (int chunk = 0; chunk < 8; chunk++) {
        const __nv_bfloat16* tAH = (chunk < 4) ? g_aggH : XH;
        const __nv_bfloat16* tAL = (chunk < 4) ? g_aggL : XL;
        int colA = (chunk & 3) * 32;

        // A: 128 rows x 32 cols, hi+lo (512 uint4 each)
        #pragma unroll
        for (int it = 0; it < 2; it++) {
            int u = it * 256 + tid;
            int r = u >> 2, c8 = (u & 3) * 8;
            size_t g = (size_t)(tileM + r) * 128 + colA + c8;
            *(uint4*)(sAH + r * AST + c8) = *(const uint4*)(tAH + g);
            *(uint4*)(sAL + r * AST + c8) = *(const uint4*)(tAL + g);
        }
        // B: 64 rows x 32 cols, hi+lo (256 uint4 each)
        {
            int r = tid >> 2, c8 = (tid & 3) * 8;
            size_t g = (size_t)(tileN + r) * 256 + chunk * 32 + c8;
            *(uint4*)(sBH + r * BST + c8) = *(const uint4*)(g_WtH + g);
            *(uint4*)(sBL + r * BST + c8) = *(const uint4*)(g_WtL + g);
        }
        __syncthreads();

        #pragma unroll
        for (int ks = 0; ks < 2; ks++) {
            int kb = ks * 16;
            wmma::fragment<wmma::matrix_a, 16, 16, 16, __nv_bfloat16, wmma::row_major> aH[2], aL[2];
            wmma::fragment<wmma::matrix_b, 16, 16, 16, __nv_bfloat16, wmma::col_major> bH[2], bL[2];
            #pragma unroll
            for (int m = 0; m < 2; m++) {
                wmma::load_matrix_sync(aH[m], sAH + (warpM * 32 + m * 16) * AST + kb, AST);
                wmma::load_matrix_sync(aL[m], sAL + (warpM * 32 + m * 16) * AST + kb, AST);
            }
            #pragma unroll
            for (int n = 0; n < 2; n++) {
                wmma::load_matrix_sync(bH[n], sBH + (warpN * 32 + n * 16) * BST + kb, BST);
                wmma::load_matrix_sync(bL[n], sBL + (warpN * 32 + n * 16) * BST + kb, BST);
            }
            #pragma unroll
            for (int m = 0; m < 2; m++)
                #pragma unroll
                for (int n = 0; n < 2; n++) {
                    wmma::mma_sync(acc[m][n], aH[m], bH[n], acc[m][n]);
                    wmma::mma_sync(acc[m][n], aH[m], bL[n], acc[m][n]);
                    wmma::mma_sync(acc[m][n], aL[m], bH[n], acc[m][n]);
                }
        }
        __syncthreads();
    }

    if (Ncol == 128) {
        // bias dropped (BN-invariant); h buffers are NPAD rows -> no row guard
        float* outp = sel_out(selOut, extOut);
        #pragma unroll
        for (int m = 0; m < 2; m++)
            #pragma unroll
            for (int n = 0; n < 2; n++)
                wmma::store_matrix_sync(
                    outp + (size_t)(tileM + warpM * 32 + m * 16) * 128
                         + tileN + warpN * 32 + n * 16,
                    acc[m][n], 128, wmma::mem_row_major);
    } else {
        // layer 2: stash to smem, then fused bias + log_softmax
        #pragma unroll
        for (int m = 0; m < 2; m++)
            #pragma unroll
            for (int n = 0; n < 2; n++)
                wmma::store_matrix_sync(
                    sE + (warpM * 32 + m * 16) * 64 + warpN * 32 + n * 16,
                    acc[m][n], 64, wmma::mem_row_major);
        __syncthreads();

        for (int i = 0; i < 16; i++) {
            int r = wid * 16 + i;
            int row = tileM + r;
            float v0 = (lid < 47)      ? sE[r * 64 + lid]      + bias[lid]      : -1e30f;
            float v1 = (lid + 32 < 47) ? sE[r * 64 + lid + 32] + bias[lid + 32] : -1e30f;
            float mx = fmaxf(v0, v1);
            #pragma unroll
            for (int off = 16; off > 0; off >>= 1)
                mx = fmaxf(mx, __shfl_xor_sync(0xffffffffu, mx, off));
            float s = ((lid < 47) ? expf(v0 - mx) : 0.f) + ((lid + 32 < 47) ? expf(v1 - mx) : 0.f);
            #pragma unroll
            for (int off = 16; off > 0; off >>= 1)
                s += __shfl_xor_sync(0xffffffffu, s, off);
            float l = mx + logf(s);
            if (row < Nrows) {
                if (lid < 47)      extOut[(size_t)row * 47 + lid]      = v0 - l;
                if (lid + 32 < 47) extOut[(size_t)row * 47 + lid + 32] = v1 - l;
            }
        }
    }
}

// ---------------- BatchNorm ----------------
__global__ void k_bnreduce(int selH, int Nrows) {
    const float* h = sel_in(selH, (const float*)0);
    __shared__ float ssum[256], ssq[256];
    int col  = threadIdx.x & 127;
    int half = threadIdx.x >> 7;
    float s = 0.f, q = 0.f;
    for (int r = blockIdx.x * 2 + half; r < Nrows; r += gridDim.x * 2) {
        float v = h[(size_t)r * DIMF + col];
        s += v; q += v * v;
    }
    ssum[threadIdx.x] = s; ssq[threadIdx.x] = q;
    __syncthreads();
    if (threadIdx.x < 128) {
        atomicAdd(&g_colsum[col], ssum[threadIdx.x] + ssum[threadIdx.x + 128]);
        atomicAdd(&g_colsq[col],  ssq[threadIdx.x]  + ssq[threadIdx.x + 128]);
    }
}
// bn+relu (scale/shift derived in-block from colsum/colsq; no bnfinal kernel).
// writes fp32 h (for aggregation) AND bf16 splits (next GEMM X operand)
__global__ void k_bnapply(int selH, const float* __restrict__ gw,
                          const float* __restrict__ be, int Nrows) {
    __shared__ float s_scale[DIMF], s_shift[DIMF];
    if (threadIdx.x < DIMF) {
        int i = threadIdx.x;
        float invn = 1.f / (float)Nrows;
        float mu  = g_colsum[i] * invn;
        float var = g_colsq[i] * invn - mu * mu;
        float rs  = rsqrtf(var + 1e-5f);
        float sc  = rs * gw[i];
        s_scale[i] = sc;
        s_shift[i] = be[i] - mu * sc;
    }
    __syncthreads();
    float* h = sel_out(selH, (float*)0);
    int idx = blockIdx.x * blockDim.x + threadIdx.x;  // float4 index
    if (idx >= Nrows * 32) return;
    int col = (idx * 4) & 127;
    float4 v  = ((float4*)h)[idx];
    float4 sc = *(const float4*)&s_scale[col];
    float4 sh = *(const float4*)&s_shift[col];
    v.x = fmaxf(v.x * sc.x + sh.x, 0.f);
    v.y = fmaxf(v.y * sc.y + sh.y, 0.f);
    v.z = fmaxf(v.z * sc.z + sh.z, 0.f);
    v.w = fmaxf(v.w * sc.w + sh.w, 0.f);
    ((float4*)h)[idx] = v;
    union { __nv_bfloat16 b[4]; uint2 u; } ph, pl;
    split2(v.x, ph.b[0], pl.b[0]);
    split2(v.y, ph.b[1], pl.b[1]);
    split2(v.z, ph.b[2], pl.b[2]);
    split2(v.w, ph.b[3], pl.b[3]);
    ((uint2*)g_hH)[idx] = ph.u;
    ((uint2*)g_hL)[idx] = pl.u;
}

// ---------------- driver ----------------
extern "C" void kernel_launch(void* const* d_in, const int* in_sizes, int n_in,
                              void* d_out, int out_size) {
    const float* x  = (const float*)d_in[0];
    const int*   ei = (const int*)d_in[1];   // int32 (JAX x64-disabled)
    const float* Wl0 = (const float*)d_in[2];
    const float* bl0 = (const float*)d_in[3];
    const float* Wr0 = (const float*)d_in[4];
    const float* g0  = (const float*)d_in[5];
    const float* be0 = (const float*)d_in[6];
    const float* Wl1 = (const float*)d_in[7];
    const float* bl1 = (const float*)d_in[8];
    const float* Wr1 = (const float*)d_in[9];
    const float* g1  = (const float*)d_in[10];
    const float* be1 = (const float*)d_in[11];
    const float* Wl2 = (const float*)d_in[12];
    const float* bl2 = (const float*)d_in[13];
    const float* Wr2 = (const float*)d_in[14];
    float* out = (float*)d_out;

    int N = in_sizes[0] / DIMF;
    int E = in_sizes[1] / 2;
    if (N > NMAX) N = NMAX;
    if (E > EMAX) E = EMAX;
    const int* srcp = ei;
    const int* dstp = ei + E;
    (void)bl0; (void)bl1;  // folded out by BN invariance

    int nb1024     = (N + 1023) / 1024;
    int aggBlocks  = (N + 7) / 8;
    int mTiles     = (N + 127) / 128;
    int convBlocks = (N * 32 + 255) / 256;
    dim3 gemmGrid2(mTiles, 2);   // Ncol=128
    dim3 gemmGrid1(mTiles, 1);   // Ncol=47

    // --- convX (also zeroes g_cnt), then CSR build ---
    k_convX<<<convBlocks, 256>>>(x, N);
    k_hist<<<(E + 255) / 256, 256>>>(dstp, E, N);
    k_scan1<<<nb1024, 1024>>>(N);
    k_scan2<<<1, 128>>>(nb1024);
    k_scan3<<<nb1024, 1024>>>(N, E);
    k_fill<<<(E + 255) / 256, 256>>>(srcp, dstp, E, N);

    // --- layer 0: agg(x) -> splits; h0 = mma(aggS, xS) ---
    k_convW<<<(128 * 256 + 255) / 256, 256>>>(Wl0, Wr0, 128);
    k_aggregate<<<aggBlocks, 256>>>(x, 0, N);
    k_mma<<<gemmGrid2, 256>>>(0, bl0, (float*)0, 1, N, 128);
    k_bnreduce<<<512, 256>>>(1, N);
    k_bnapply<<<convBlocks, 256>>>(1, g0, be0, N);

    // --- layer 1: agg(h0); h1 = mma(aggS, hS) ---
    k_convW<<<(128 * 256 + 255) / 256, 256>>>(Wl1, Wr1, 128);
    k_aggregate<<<aggBlocks, 256>>>((const float*)0, 1, N);
    k_mma<<<gemmGrid2, 256>>>(1, bl1, (float*)0, 2, N, 128);
    k_bnreduce<<<512, 256>>>(2, N);
    k_bnapply<<<convBlocks, 256>>>(2, g1, be1, N);

    // --- layer 2: agg(h1); out = log_softmax(mma(aggS, hS) + bias) (fused) ---
    k_convW<<<(128 * 256 + 255) / 256, 256>>>(Wl2, Wr2, 47);
    k_aggregate<<<aggBlocks, 256>>>((const float*)0, 2, N);
    k_mma<<<gemmGrid1, 256>>>(1, bl2, out, 0, N, 47);
}

// round 16
// speedup vs baseline: 1.2351x; 1.1775x over previous
#include <cuda_runtime.h>
#include <cuda_bf16.h>
#include <mma.h>
#include <cstdint>
#include <math.h>

using namespace nvcuda;

#define NMAX 100000
#define NPAD 100096      // 782*128
#define EMAX 1600000
#define DIMF 128

// ---------------- static scratch (no allocations allowed) ----------------
__device__ __align__(16) float g_h0 [(size_t)NPAD * DIMF];
__device__ __align__(16) float g_h1 [(size_t)NPAD * DIMF];
// bf16 split tables (hi/lo), padded rows zero-initialized (bss)
__device__ __align__(16) __nv_bfloat16 g_aggH[(size_t)NPAD * DIMF];
__device__ __align__(16) __nv_bfloat16 g_aggL[(size_t)NPAD * DIMF];
__device__ __align__(16) __nv_bfloat16 g_xH  [(size_t)NPAD * DIMF];
__device__ __align__(16) __nv_bfloat16 g_xL  [(size_t)NPAD * DIMF];
__device__ __align__(16) __nv_bfloat16 g_hH  [(size_t)NPAD * DIMF];
__device__ __align__(16) __nv_bfloat16 g_hL  [(size_t)NPAD * DIMF];
// weights transposed+concatenated: [128 rows (out col), 256 cols (k)] bf16
__device__ __align__(16) __nv_bfloat16 g_WtH[128 * 256];
__device__ __align__(16) __nv_bfloat16 g_WtL[128 * 256];

__device__ int   g_cnt[NMAX];
__device__ int   g_rowptr[NMAX + 1];
__device__ int   g_cursor[NMAX];
__device__ int   g_csr[EMAX];
__device__ int   g_bsum[128];
__device__ int   g_bsumx[128];
__device__ __align__(16) float g_colsum[DIMF];
__device__ __align__(16) float g_colsq[DIMF];

// sel: 0 = external ptr, 1 = g_h0, 2 = g_h1
__device__ __forceinline__ const float* sel_in(int s, const float* ext) {
    if (s == 1) return g_h0;
    if (s == 2) return g_h1;
    return ext;
}
__device__ __forceinline__ float* sel_out(int s, float* ext) {
    if (s == 1) return g_h0;
    if (s == 2) return g_h1;
    return ext;
}

// split a float into bf16 hi + bf16 lo
__device__ __forceinline__ void split2(float a, __nv_bfloat16& h, __nv_bfloat16& l) {
    h = __float2bfloat16(a);
    l = __float2bfloat16(a - __bfloat162float(h));
}

// ---------------- cp.async helpers (baseline PTX, sm_80+) ----------------
__device__ __forceinline__ uint32_t smem_u32(const void* p) {
    uint32_t a;
    asm("{ .reg .u64 t; cvta.to.shared.u64 t, %1; cvt.u32.u64 %0, t; }" : "=r"(a) : "l"(p));
    return a;
}
__device__ __forceinline__ void cp16(uint32_t saddr, const void* gaddr) {
    asm volatile("cp.async.cg.shared.global [%0], [%1], 16;" :: "r"(saddr), "l"(gaddr));
}
__device__ __forceinline__ void cp_commit() {
    asm volatile("cp.async.commit_group;" ::: "memory");
}
template <int N>
__device__ __forceinline__ void cp_wait() {
    asm volatile("cp.async.wait_group %0;" :: "n"(N) : "memory");
}

// ---------------- conversions (k_convX also zeroes g_cnt for CSR build) ----------------
__global__ void k_convX(const float* __restrict__ x, int Nrows) {
    int idx = blockIdx.x * blockDim.x + threadIdx.x;  // float4 index
    if (idx < NMAX) g_cnt[idx] = 0;
    int idx2 = idx + (int)(gridDim.x * blockDim.x);
    if (idx2 < NMAX) g_cnt[idx2] = 0;
    if (idx >= Nrows * 32) return;
    float4 v = ((const float4*)x)[idx];
    union { __nv_bfloat16 h[4]; uint2 u; } ph, pl;
    split2(v.x, ph.h[0], pl.h[0]);
    split2(v.y, ph.h[1], pl.h[1]);
    split2(v.z, ph.h[2], pl.h[2]);
    split2(v.w, ph.h[3], pl.h[3]);
    ((uint2*)g_xH)[idx] = ph.u;
    ((uint2*)g_xL)[idx] = pl.u;
}

// weights: Wt[n][k] = k<128 ? Wl[k][n] : Wr[k-128][n], n beyond Ncol -> 0
// also zeroes BN column accumulators for this layer (filled by k_mma epilogue)
__global__ void k_convW(const float* __restrict__ Wl, const float* __restrict__ Wr, int Ncol) {
    int idx = blockIdx.x * blockDim.x + threadIdx.x;  // over 128*256
    if (blockIdx.x == 0 && threadIdx.x < DIMF) {
        g_colsum[threadIdx.x] = 0.f;
        g_colsq[threadIdx.x]  = 0.f;
    }
    if (idx >= 128 * 256) return;
    int n = idx >> 8, k = idx & 255;
    float v = 0.f;
    if (n < Ncol) v = (k < 128) ? Wl[k * Ncol + n] : Wr[(k - 128) * Ncol + n];
    __nv_bfloat16 h, l;
    split2(v, h, l);
    g_WtH[idx] = h;
    g_WtL[idx] = l;
}

// ---------------- CSR build ----------------
__global__ void k_hist(const int* __restrict__ dst, int E, int n) {
    int e = blockIdx.x * blockDim.x + threadIdx.x;
    if (e < E) {
        unsigned d = (unsigned)dst[e];
        if (d < (unsigned)n) atomicAdd(&g_cnt[d], 1);
    }
}
__global__ __launch_bounds__(1024) void k_scan1(int n) {
    __shared__ int s[1024];
    int i = blockIdx.x * 1024 + threadIdx.x;
    int v = (i < n) ? g_cnt[i] : 0;
    s[threadIdx.x] = v;
    __syncthreads();
    #pragma unroll
    for (int off = 1; off < 1024; off <<= 1) {
        int t = (threadIdx.x >= off) ? s[threadIdx.x - off] : 0;
        __syncthreads();
        s[threadIdx.x] += t;
        __syncthreads();
    }
    if (i < n) g_rowptr[i] = s[threadIdx.x] - v;
    if (threadIdx.x == 1023) g_bsum[blockIdx.x] = s[1023];
}
__global__ void k_scan2(int nb) {
    __shared__ int s[128];
    int v = (threadIdx.x < nb) ? g_bsum[threadIdx.x] : 0;
    s[threadIdx.x] = v;
    __syncthreads();
    #pragma unroll
    for (int off = 1; off < 128; off <<= 1) {
        int t = (threadIdx.x >= off) ? s[threadIdx.x - off] : 0;
        __syncthreads();
        s[threadIdx.x] += t;
        __syncthreads();
    }
    if (threadIdx.x < nb) g_bsumx[threadIdx.x] = s[threadIdx.x] - v;
}
__global__ __launch_bounds__(1024) void k_scan3(int n, int E) {
    int i = blockIdx.x * 1024 + threadIdx.x;
    if (i < n) {
        int v = g_rowptr[i] + g_bsumx[i >> 10];
        g_rowptr[i] = v;
        g_cursor[i] = v;
    }
    if (i == 0) g_rowptr[n] = E;
}
__global__ void k_fill(const int* __restrict__ src, const int* __restrict__ dst, int E, int n) {
    int e = blockIdx.x * blockDim.x + threadIdx.x;
    if (e < E) {
        unsigned d = (unsigned)dst[e];
        unsigned s = (unsigned)src[e];
        if (d < (unsigned)n && s < (unsigned)n) {
            int p = atomicAdd(&g_cursor[d], 1);
            g_csr[p] = (int)s;
        }
    }
}

// ---------------- mean aggregation -> bf16 split tables ----------------
// 1 warp per node. Scalar index load is a warp-uniform broadcast; row gathers
// are independent (high MLP). LTS-bandwidth-bound — do not "optimize" (r14).
__global__ void k_aggregate(const float* __restrict__ ext, int selIn, int n) {
    int gw   = (blockIdx.x * blockDim.x + threadIdx.x) >> 5;
    int lane = threadIdx.x & 31;
    if (gw >= n) return;
    const float* in = sel_in(selIn, ext);
    int s0 = g_rowptr[gw], s1 = g_rowptr[gw + 1];
    float4 acc = make_float4(0.f, 0.f, 0.f, 0.f);
    const float4* base = (const float4*)in;
    for (int e = s0; e < s1; e++) {
        int s = g_csr[e];
        float4 v = __ldg(&base[(size_t)s * 32 + lane]);
        acc.x += v.x; acc.y += v.y; acc.z += v.z; acc.w += v.w;
    }
    float inv = 1.f / fmaxf((float)(s1 - s0), 1.f);
    acc.x *= inv; acc.y *= inv; acc.z *= inv; acc.w *= inv;
    union { __nv_bfloat16 h[4]; uint2 u; } ph, pl;
    split2(acc.x, ph.h[0], pl.h[0]);
    split2(acc.y, ph.h[1], pl.h[1]);
    split2(acc.z, ph.h[2], pl.h[2]);
    split2(acc.w, ph.h[3], pl.h[3]);
    size_t o = (size_t)gw * 32 + lane;
    ((uint2*)g_aggH)[o] = ph.u;
    ((uint2*)g_aggL)[o] = pl.u;
}

// ---------------- WMMA bf16x3 GEMM, 2-stage cp.async pipeline ----------------
// out[128, 64-tile] = [agg | X](128x256) @ Wt(ncol x 256)^T
// 8 warps 4x2, warp tile 32x32. 8 K-chunks of 32, double-buffered.
// Stage layout (bytes, stride 80B = 40 bf16 elems, conflict-free for LDSM):
//   AH 0..10239, AL 10240..20479, BH 20480..25599, BL 25600..30719
// Two stages = 61440 B dynamic smem. Epilogue overlays stage memory.
#define AST 40
#define STAGE_B 30720
#define SMEM_MMA (2 * STAGE_B)

struct MmaSrc { const __nv_bfloat16 *aggH, *aggL, *xH, *xL; };

__device__ __forceinline__ void issue_chunk(
    uint32_t sbase, char* dsm_unused, int chunk, int tid, int tileM, int tileN,
    const __nv_bfloat16* XH, const __nv_bfloat16* XL)
{
    const __nv_bfloat16* tAH = (chunk < 4) ? g_aggH : XH;
    const __nv_bfloat16* tAL = (chunk < 4) ? g_aggL : XL;
    int colA = (chunk & 3) * 32;
    #pragma unroll
    for (int k = 0; k < 6; k++) {
        int u = tid + k * 256;
        if (u < 1024) {
            int split = u >> 9, v = u & 511;
            int r = v >> 2, c16 = v & 3;
            const __nv_bfloat16* g = (split ? tAL : tAH)
                + (size_t)(tileM + r) * 128 + colA + c16 * 8;
            cp16(sbase + split * 10240 + r * 80 + c16 * 16, g);
        } else {
            int w = u - 1024;
            int split = w >> 8, v = w & 255;
            int r = v >> 2, c16 = v & 3;
            const __nv_bfloat16* g = (split ? g_WtL : g_WtH)
                + (size_t)(tileN + r) * 256 + chunk * 32 + c16 * 8;
            cp16(sbase + 20480 + split * 5120 + r * 80 + c16 * 16, g);
        }
    }
}

__global__ __launch_bounds__(256) void k_mma(
    int selX, const float* __restrict__ bias,
    float* __restrict__ extOut, int selOut,
    int Nrows, int Ncol)
{
    extern __shared__ __align__(16) char dsm[];
    uint32_t sb0 = smem_u32(dsm);

    int tid = threadIdx.x;
    int wid = tid >> 5, lid = tid & 31;
    int tileM = blockIdx.x * 128;
    int tileN = blockIdx.y * 64;
    int warpM = wid >> 1;   // 0..3
    int warpN = wid & 1;    // 0..1

    const __nv_bfloat16* XH = selX ? g_hH : g_xH;
    const __nv_bfloat16* XL = selX ? g_hL : g_xL;

    wmma::fragment<wmma::accumulator, 16, 16, 16, float> acc[2][2];
    #pragma unroll
    for (int m = 0; m < 2; m++)
        #pragma unroll
        for (int n = 0; n < 2; n++)
            wmma::fill_fragment(acc[m][n], 0.f);

    // prologue: stage chunks 0 and 1
    issue_chunk(sb0, dsm, 0, tid, tileM, tileN, XH, XL);
    cp_commit();
    issue_chunk(sb0 + STAGE_B, dsm, 1, tid, tileM, tileN, XH, XL);
    cp_commit();

    for (int c = 0; c < 8; c++) {
        if (c < 7) cp_wait<1>(); else cp_wait<0>();
        __syncthreads();

        char* stg = dsm + (c & 1) * STAGE_B;
        __nv_bfloat16* sAH = (__nv_bfloat16*)stg;
        __nv_bfloat16* sAL = (__nv_bfloat16*)(stg + 10240);
        __nv_bfloat16* sBH = (__nv_bfloat16*)(stg + 20480);
        __nv_bfloat16* sBL = (__nv_bfloat16*)(stg + 25600);

        #pragma unroll
        for (int ks = 0; ks < 2; ks++) {
            int kb = ks * 16;
            wmma::fragment<wmma::matrix_a, 16, 16, 16, __nv_bfloat16, wmma::row_major> aH[2], aL[2];
            wmma::fragment<wmma::matrix_b, 16, 16, 16, __nv_bfloat16, wmma::col_major> bH[2], bL[2];
            #pragma unroll
            for (int m = 0; m < 2; m++) {
                wmma::load_matrix_sync(aH[m], sAH + (warpM * 32 + m * 16) * AST + kb, AST);
                wmma::load_matrix_sync(aL[m], sAL + (warpM * 32 + m * 16) * AST + kb, AST);
            }
            #pragma unroll
            for (int n = 0; n < 2; n++) {
                wmma::load_matrix_sync(bH[n], sBH + (warpN * 32 + n * 16) * AST + kb, AST);
                wmma::load_matrix_sync(bL[n], sBL + (warpN * 32 + n * 16) * AST + kb, AST);
            }
            #pragma unroll
            for (int m = 0; m < 2; m++)
                #pragma unroll
                for (int n = 0; n < 2; n++) {
                    wmma::mma_sync(acc[m][n], aH[m], bH[n], acc[m][n]);
                    wmma::mma_sync(acc[m][n], aH[m], bL[n], acc[m][n]);
                    wmma::mma_sync(acc[m][n], aL[m], bH[n], acc[m][n]);
                }
        }
        __syncthreads();
        if (c + 2 < 8) {
            issue_chunk(sb0 + ((c & 1) ? STAGE_B : 0), dsm, c + 2, tid, tileM, tileN, XH, XL);
            cp_commit();
        }
    }

    // ---------------- epilogue ----------------
    float* sE = (float*)dsm;   // 128x64 f32 = 32 KB (stages dead now)

    #pragma unroll
    for (int m = 0; m < 2; m++)
        #pragma unroll
        for (int n = 0; n < 2; n++)
            wmma::store_matrix_sync(
                sE + (warpM * 32 + m * 16) * 64 + warpN * 32 + n * 16,
                acc[m][n], 64, wmma::mem_row_major);
    __syncthreads();

    if (Ncol == 128) {
        // fused BN column sums: 64 cols x 4 row-parts per thread, shfl-combined
        {
            int col = tid >> 2, part = tid & 3;
            float s = 0.f, q = 0.f;
            int r0 = part * 32;
            #pragma unroll 8
            for (int r = r0; r < r0 + 32; r++) {
                float v = sE[r * 64 + col];
                s += v; q += v * v;
            }
            s += __shfl_xor_sync(0xffffffffu, s, 1);
            s += __shfl_xor_sync(0xffffffffu, s, 2);
            q += __shfl_xor_sync(0xffffffffu, q, 1);
            q += __shfl_xor_sync(0xffffffffu, q, 2);
            if (part == 0) {
                atomicAdd(&g_colsum[tileN + col], s);
                atomicAdd(&g_colsq [tileN + col], q);
            }
        }
        // coalesced tile store (pad rows < NPAD, safe)
        float* outp = sel_out(selOut, extOut);
        #pragma unroll
        for (int it = 0; it < 8; it++) {
            int u = it * 256 + tid;          // float4 units: 128 rows x 16
            int r = u >> 4, c4 = u & 15;
            *(float4*)(outp + (size_t)(tileM + r) * 128 + tileN + c4 * 4) =
                *(float4*)(sE + r * 64 + c4 * 4);
        }
    } else {
        // layer 2: fused bias + log_softmax
        for (int i = 0; i < 16; i++) {
            int r = wid * 16 + i;
            int row = tileM + r;
            float v0 = (lid < 47)      ? sE[r * 64 + lid]      + bias[lid]      : -1e30f;
            float v1 = (lid + 32 < 47) ? sE[r * 64 + lid + 32] + bias[lid + 32] : -1e30f;
            float mx = fmaxf(v0, v1);
            #pragma unroll
            for (int off = 16; off > 0; off >>= 1)
                mx = fmaxf(mx, __shfl_xor_sync(0xffffffffu, mx, off));
            float s = ((lid < 47) ? expf(v0 - mx) : 0.f) + ((lid + 32 < 47) ? expf(v1 - mx) : 0.f);
            #pragma unroll
            for (int off = 16; off > 0; off >>= 1)
                s += __shfl_xor_sync(0xffffffffu, s, off);
            float l = mx + logf(s);
            if (row < Nrows) {
                if (lid < 47)      extOut[(size_t)row * 47 + lid]      = v0 - l;
                if (lid + 32 < 47) extOut[(size_t)row * 47 + lid + 32] = v1 - l;
            }
        }
    }
}

// ---------------- BatchNorm apply (sums come from k_mma epilogue) ----------------
__global__ void k_bnapply(int selH, const float* __restrict__ gw,
                          const float* __restrict__ be, int Nrows) {
    __shared__ float s_scale[DIMF], s_shift[DIMF];
    if (threadIdx.x < DIMF) {
        int i = threadIdx.x;
        float invn = 1.f / (float)Nrows;
        float mu  = g_colsum[i] * invn;
        float var = g_colsq[i] * invn - mu * mu;
        float rs  = rsqrtf(var + 1e-5f);
        float sc  = rs * gw[i];
        s_scale[i] = sc;
        s_shift[i] = be[i] - mu * sc;
    }
    __syncthreads();
    float* h = sel_out(selH, (float*)0);
    int idx = blockIdx.x * blockDim.x + threadIdx.x;  // float4 index
    if (idx >= Nrows * 32) return;
    int col = (idx * 4) & 127;
    float4 v  = ((float4*)h)[idx];
    float4 sc = *(const float4*)&s_scale[col];
    float4 sh = *(const float4*)&s_shift[col];
    v.x = fmaxf(v.x * sc.x + sh.x, 0.f);
    v.y = fmaxf(v.y * sc.y + sh.y, 0.f);
    v.z = fmaxf(v.z * sc.z + sh.z, 0.f);
    v.w = fmaxf(v.w * sc.w + sh.w, 0.f);
    ((float4*)h)[idx] = v;
    union { __nv_bfloat16 b[4]; uint2 u; } ph, pl;
    split2(v.x, ph.b[0], pl.b[0]);
    split2(v.y, ph.b[1], pl.b[1]);
    split2(v.z, ph.b[2], pl.b[2]);
    split2(v.w, ph.b[3], pl.b[3]);
    ((uint2*)g_hH)[idx] = ph.u;
    ((uint2*)g_hL)[idx] = pl.u;
}

// ---------------- driver ----------------
extern "C" void kernel_launch(void* const* d_in, const int* in_sizes, int n_in,
                              void* d_out, int out_size) {
    const float* x  = (const float*)d_in[0];
    const int*   ei = (const int*)d_in[1];   // int32 (JAX x64-disabled)
    const float* Wl0 = (const float*)d_in[2];
    const float* bl0 = (const float*)d_in[3];
    const float* Wr0 = (const float*)d_in[4];
    const float* g0  = (const float*)d_in[5];
    const float* be0 = (const float*)d_in[6];
    const float* Wl1 = (const float*)d_in[7];
    const float* bl1 = (const float*)d_in[8];
    const float* Wr1 = (const float*)d_in[9];
    const float* g1  = (const float*)d_in[10];
    const float* be1 = (const float*)d_in[11];
    const float* Wl2 = (const float*)d_in[12];
    const float* bl2 = (const float*)d_in[13];
    const float* Wr2 = (const float*)d_in[14];
    float* out = (float*)d_out;

    int N = in_sizes[0] / DIMF;
    int E = in_sizes[1] / 2;
    if (N > NMAX) N = NMAX;
    if (E > EMAX) E = EMAX;
    const int* srcp = ei;
    const int* dstp = ei + E;
    (void)bl0; (void)bl1;  // folded out by BN invariance

    cudaFuncSetAttribute(k_mma, cudaFuncAttributeMaxDynamicSharedMemorySize, SMEM_MMA);

    int nb1024     = (N + 1023) / 1024;
    int aggBlocks  = (N + 7) / 8;
    int mTiles     = (N + 127) / 128;
    int convBlocks = (N * 32 + 255) / 256;
    dim3 gemmGrid2(mTiles, 2);   // Ncol=128
    dim3 gemmGrid1(mTiles, 1);   // Ncol=47

    // --- convX (also zeroes g_cnt), then CSR build ---
    k_convX<<<convBlocks, 256>>>(x, N);
    k_hist<<<(E + 255) / 256, 256>>>(dstp, E, N);
    k_scan1<<<nb1024, 1024>>>(N);
    k_scan2<<<1, 128>>>(nb1024);
    k_scan3<<<nb1024, 1024>>>(N, E);
    k_fill<<<(E + 255) / 256, 256>>>(srcp, dstp, E, N);

    // --- layer 0: agg(x) -> splits; h0 = mma(aggS, xS); colsums fused ---
    k_convW<<<(128 * 256 + 255) / 256, 256>>>(Wl0, Wr0, 128);
    k_aggregate<<<aggBlocks, 256>>>(x, 0, N);
    k_mma<<<gemmGrid2, 256, SMEM_MMA>>>(0, bl0, (float*)0, 1, N, 128);
    k_bnapply<<<convBlocks, 256>>>(1, g0, be0, N);

    // --- layer 1 ---
    k_convW<<<(128 * 256 + 255) / 256, 256>>>(Wl1, Wr1, 128);
    k_aggregate<<<aggBlocks, 256>>>((const float*)0, 1, N);
    k_mma<<<gemmGrid2, 256, SMEM_MMA>>>(1, bl1, (float*)0, 2, N, 128);
    k_bnapply<<<convBlocks, 256>>>(2, g1, be1, N);

    // --- layer 2: fused bias + log_softmax ---
    k_convW<<<(128 * 256 + 255) / 256, 256>>>(Wl2, Wr2, 47);
    k_aggregate<<<aggBlocks, 256>>>((const float*)0, 2, N);
    k_mma<<<gemmGrid1, 256, SMEM_MMA>>>(1, bl2, out, 0, N, 47);
}